// round 3
// baseline (speedup 1.0000x reference)
#include <cuda_runtime.h>
#include <math.h>

#define Bb    2
#define Ls    4096
#define Dd    1024
#define Hh    16
#define Gg    2
#define WINs  256
#define HDd   64
#define KVd   128
#define Ee    8
#define HIDs  1024
#define NTOK  8192     // B*L
#define QROWS 2176     // only query/key rows < 2176 per batch are ever used

// ---------------- scratch (static __device__ globals; no allocs allowed) ----
__device__ float g_ln1[NTOK * Dd];
__device__ float g_qb [NTOK * Dd];
__device__ float g_kb [NTOK * KVd];
__device__ float g_vb [NTOK * KVd];
__device__ float g_ob [NTOK * Dd];
__device__ float g_ln2[NTOK * Dd];
__device__ int   g_cnt[Ee];
__device__ int   g_list[Ee][NTOK];
__device__ float g_wl  [Ee][NTOK];
__device__ float g_entsum;

// ---------------- init: zero per-replay counters ---------------------------
__global__ void init_kernel() {
    int t = threadIdx.x;
    if (t < Ee) g_cnt[t] = 0;
    if (t == 0) g_entsum = 0.f;
}

// ---------------- layernorm (one block per row, 256 thr, float4) -----------
__device__ __forceinline__ float block_reduce_sum(float v, float* sh) {
    int lane = threadIdx.x & 31, w = threadIdx.x >> 5;
    #pragma unroll
    for (int o = 16; o; o >>= 1) v += __shfl_xor_sync(0xffffffffu, v, o);
    if (lane == 0) sh[w] = v;
    __syncthreads();
    if (w == 0) {
        float r = (lane < 8) ? sh[lane] : 0.f;
        #pragma unroll
        for (int o = 4; o; o >>= 1) r += __shfl_xor_sync(0xffffffffu, r, o);
        if (lane == 0) sh[0] = r;
    }
    __syncthreads();
    float r = sh[0];
    __syncthreads();
    return r;
}

__global__ __launch_bounds__(256) void ln_kernel(
    const float* __restrict__ x, const float* __restrict__ g,
    const float* __restrict__ b, float* __restrict__ out)
{
    __shared__ float sh[8];
    size_t row = blockIdx.x;
    const float4* xr = (const float4*)(x + row * Dd);
    float4 v = xr[threadIdx.x];
    float mean = block_reduce_sum(v.x + v.y + v.z + v.w, sh) * (1.f / Dd);
    float d0 = v.x - mean, d1 = v.y - mean, d2 = v.z - mean, d3 = v.w - mean;
    float var = block_reduce_sum(d0*d0 + d1*d1 + d2*d2 + d3*d3, sh) * (1.f / Dd);
    float inv = rsqrtf(var + 1e-5f);
    float4 gv = ((const float4*)g)[threadIdx.x];
    float4 bv = ((const float4*)b)[threadIdx.x];
    float4 o;
    o.x = d0 * inv * gv.x + bv.x;
    o.y = d1 * inv * gv.y + bv.y;
    o.z = d2 * inv * gv.z + bv.z;
    o.w = d3 * inv * gv.w + bv.w;
    ((float4*)(out + row * Dd))[threadIdx.x] = o;
}

// ---------------- generic SGEMM: C = A(MxK) * B(KxN) + bias (+ res) --------
// BM=BN=128, BK=16, 256 threads, 8x8 micro-tile. Grid must cover exact tiles.
__global__ __launch_bounds__(256) void sgemm_bias(
    const float* __restrict__ A, const float* __restrict__ Bm,
    const float* __restrict__ bias, const float* __restrict__ res,
    float* __restrict__ C, int Nn, int Kk)
{
    __shared__ float As[16][128];
    __shared__ float Bs[16][128];
    int m0 = blockIdx.y * 128;
    int n0 = blockIdx.x * 128;
    int tid = threadIdx.x;
    int tx = tid & 15, ty = tid >> 4;
    float acc[8][8] = {};
    for (int k0 = 0; k0 < Kk; k0 += 16) {
        #pragma unroll
        for (int it = 0; it < 2; it++) {
            int p  = tid + it * 256;
            int ar = p >> 2, ac = (p & 3) * 4;
            float4 av = *(const float4*)&A[(size_t)(m0 + ar) * Kk + k0 + ac];
            As[ac + 0][ar] = av.x; As[ac + 1][ar] = av.y;
            As[ac + 2][ar] = av.z; As[ac + 3][ar] = av.w;
            int br = p >> 5, bc = (p & 31) * 4;
            *(float4*)&Bs[br][bc] =
                *(const float4*)&Bm[(size_t)(k0 + br) * Nn + n0 + bc];
        }
        __syncthreads();
        #pragma unroll
        for (int k = 0; k < 16; k++) {
            float a[8], bb[8];
            #pragma unroll
            for (int i = 0; i < 8; i++) a[i] = As[k][ty * 8 + i];
            #pragma unroll
            for (int j = 0; j < 8; j++) bb[j] = Bs[k][tx * 8 + j];
            #pragma unroll
            for (int i = 0; i < 8; i++)
                #pragma unroll
                for (int j = 0; j < 8; j++) acc[i][j] += a[i] * bb[j];
        }
        __syncthreads();
    }
    #pragma unroll
    for (int i = 0; i < 8; i++) {
        size_t m = m0 + ty * 8 + i;
        #pragma unroll
        for (int j4 = 0; j4 < 8; j4 += 4) {
            int n = n0 + tx * 8 + j4;
            float4 v;
            v.x = acc[i][j4 + 0] + bias[n + 0];
            v.y = acc[i][j4 + 1] + bias[n + 1];
            v.z = acc[i][j4 + 2] + bias[n + 2];
            v.w = acc[i][j4 + 3] + bias[n + 3];
            if (res) {
                float4 r = *(const float4*)&res[m * Nn + n];
                v.x += r.x; v.y += r.y; v.z += r.z; v.w += r.w;
            }
            *(float4*)&C[m * Nn + n] = v;
        }
    }
}

// ---------------- windowed GQA attention -----------------------------------
// Output row t = n*256 + w (t < 4096): query pos n*128+w, keys [n*128, n*128+256)
__global__ __launch_bounds__(256, 1) void attn_kernel(
    const float* __restrict__ Q, const float* __restrict__ K,
    const float* __restrict__ V, float* __restrict__ O)
{
    extern __shared__ float smem[];
    float* Ks = smem;
    float* Vs = smem + WINs * HDd;
    int n = blockIdx.x, h = blockIdx.y, b = blockIdx.z;
    int g = h & (Gg - 1);
    int kbase = n * (WINs / 2);
    const float* Kg = K + ((size_t)b * Ls + kbase) * KVd + g * HDd;
    const float* Vg = V + ((size_t)b * Ls + kbase) * KVd + g * HDd;
    for (int i = threadIdx.x; i < WINs * HDd / 4; i += 256) {
        int r = i >> 4, c = (i & 15) * 4;
        *(float4*)&Ks[r * HDd + c] = *(const float4*)&Kg[(size_t)r * KVd + c];
        *(float4*)&Vs[r * HDd + c] = *(const float4*)&Vg[(size_t)r * KVd + c];
    }
    __syncthreads();
    int w = threadIdx.x;
    const float* qr = Q + ((size_t)b * Ls + kbase + w) * Dd + h * HDd;
    float q[HDd], acc[HDd];
    #pragma unroll
    for (int i = 0; i < HDd; i++) { q[i] = qr[i] * 0.125f; acc[i] = 0.f; }
    float mrun = -1e30f, lrun = 0.f;
    for (int kc = 0; kc < WINs; kc += 8) {
        float s[8];
        #pragma unroll
        for (int j = 0; j < 8; j++) {
            const float* kr = &Ks[(kc + j) * HDd];
            float d = 0.f;
            #pragma unroll
            for (int i = 0; i < HDd; i++) d += q[i] * kr[i];
            s[j] = d;
        }
        float cm = s[0];
        #pragma unroll
        for (int j = 1; j < 8; j++) cm = fmaxf(cm, s[j]);
        float nm = fmaxf(mrun, cm);
        float scale = __expf(mrun - nm);
        lrun *= scale;
        #pragma unroll
        for (int i = 0; i < HDd; i++) acc[i] *= scale;
        #pragma unroll
        for (int j = 0; j < 8; j++) {
            float ev = __expf(s[j] - nm);
            lrun += ev;
            const float* vr = &Vs[(kc + j) * HDd];
            #pragma unroll
            for (int i = 0; i < HDd; i++) acc[i] += ev * vr[i];
        }
        mrun = nm;
    }
    float inv = 1.f / lrun;
    float* orow = O + ((size_t)b * Ls + n * WINs + w) * Dd + h * HDd;
    #pragma unroll
    for (int i = 0; i < HDd; i += 4) {
        float4 o4 = make_float4(acc[i] * inv, acc[i+1] * inv,
                                acc[i+2] * inv, acc[i+3] * inv);
        *(float4*)&orow[i] = o4;
    }
}

// ---------------- gating: warp per token ------------------------------------
__global__ __launch_bounds__(256) void gate_kernel(
    const float* __restrict__ X, const float* __restrict__ Wg,
    const float* __restrict__ bg)
{
    int tok  = (blockIdx.x * 256 + threadIdx.x) >> 5;
    int lane = threadIdx.x & 31;
    if (tok >= NTOK) return;
    const float* xr = X + (size_t)tok * Dd;
    float a[Ee];
    #pragma unroll
    for (int e = 0; e < Ee; e++) a[e] = 0.f;
    for (int d = lane; d < Dd; d += 32) {
        float xv = xr[d];
        const float4* wr = (const float4*)&Wg[d * Ee];
        float4 w0 = wr[0], w1 = wr[1];
        a[0] += xv * w0.x; a[1] += xv * w0.y; a[2] += xv * w0.z; a[3] += xv * w0.w;
        a[4] += xv * w1.x; a[5] += xv * w1.y; a[6] += xv * w1.z; a[7] += xv * w1.w;
    }
    #pragma unroll
    for (int e = 0; e < Ee; e++)
        #pragma unroll
        for (int o = 16; o; o >>= 1) a[e] += __shfl_xor_sync(0xffffffffu, a[e], o);
    if (lane == 0) {
        float mx = -1e30f;
        #pragma unroll
        for (int e = 0; e < Ee; e++) { a[e] += bg[e]; mx = fmaxf(mx, a[e]); }
        float p[Ee], se = 0.f;
        #pragma unroll
        for (int e = 0; e < Ee; e++) { p[e] = __expf(a[e] - mx); se += p[e]; }
        float inv = 1.f / se, ent = 0.f;
        #pragma unroll
        for (int e = 0; e < Ee; e++) { p[e] *= inv; ent -= p[e] * logf(p[e] + 1e-8f); }
        atomicAdd(&g_entsum, ent);
        int i0 = 0;
        #pragma unroll
        for (int e = 1; e < Ee; e++) if (p[e] > p[i0]) i0 = e;
        int i1 = -1;
        #pragma unroll
        for (int e = 0; e < Ee; e++) {
            if (e == i0) continue;
            if (i1 < 0 || p[e] > p[i1]) i1 = e;
        }
        int p0 = atomicAdd(&g_cnt[i0], 1);
        g_list[i0][p0] = tok; g_wl[i0][p0] = p[i0];
        int p1 = atomicAdd(&g_cnt[i1], 1);
        g_list[i1][p1] = tok; g_wl[i1][p1] = p[i1];
    }
}

// ---------------- grouped MoE GEMM: out[tok] += w * (x @ We[e] + be[e]) -----
__global__ __launch_bounds__(256) void moe_gemm(
    const float* __restrict__ X, const float* __restrict__ We,
    const float* __restrict__ be, float* __restrict__ out)
{
    int e = blockIdx.z;
    int cnt = g_cnt[e];
    int m0 = blockIdx.y * 128;
    if (m0 >= cnt) return;
    int n0 = blockIdx.x * 128;
    const float* Bm = We + (size_t)e * Dd * HIDs;
    __shared__ float As[16][128];
    __shared__ float Bs[16][128];
    __shared__ int ridx[128];
    int tid = threadIdx.x;
    if (tid < 128) {
        int m = m0 + tid;
        ridx[tid] = (m < cnt) ? g_list[e][m] : -1;
    }
    __syncthreads();
    int tx = tid & 15, ty = tid >> 4;
    float acc[8][8] = {};
    for (int k0 = 0; k0 < Dd; k0 += 16) {
        #pragma unroll
        for (int it = 0; it < 2; it++) {
            int p  = tid + it * 256;
            int ar = p >> 2, ac = (p & 3) * 4;
            int tk = ridx[ar];
            float4 av = make_float4(0.f, 0.f, 0.f, 0.f);
            if (tk >= 0) av = *(const float4*)&X[(size_t)tk * Dd + k0 + ac];
            As[ac + 0][ar] = av.x; As[ac + 1][ar] = av.y;
            As[ac + 2][ar] = av.z; As[ac + 3][ar] = av.w;
            int br = p >> 5, bc = (p & 31) * 4;
            *(float4*)&Bs[br][bc] =
                *(const float4*)&Bm[(size_t)(k0 + br) * HIDs + n0 + bc];
        }
        __syncthreads();
        #pragma unroll
        for (int k = 0; k < 16; k++) {
            float a[8], bb[8];
            #pragma unroll
            for (int i = 0; i < 8; i++) a[i] = As[k][ty * 8 + i];
            #pragma unroll
            for (int j = 0; j < 8; j++) bb[j] = Bs[k][tx * 8 + j];
            #pragma unroll
            for (int i = 0; i < 8; i++)
                #pragma unroll
                for (int j = 0; j < 8; j++) acc[i][j] += a[i] * bb[j];
        }
        __syncthreads();
    }
    #pragma unroll
    for (int i = 0; i < 8; i++) {
        int m = m0 + ty * 8 + i;
        if (m >= cnt) continue;
        int tk = ridx[ty * 8 + i];
        float w = g_wl[e][m];
        float* orow = out + (size_t)tk * HIDs + n0;
        #pragma unroll
        for (int j = 0; j < 8; j++) {
            int nn = tx * 8 + j;
            atomicAdd(&orow[nn], w * (acc[i][j] + be[e * HIDs + n0 + nn]));
        }
    }
}

// ---------------- aux scalar ------------------------------------------------
__global__ void fin_kernel(float* __restrict__ out) {
    float pen = 0.f;
    #pragma unroll
    for (int e = 0; e < Ee; e++) {
        float usage = (float)g_cnt[e] / (8192.f + 1e-8f);
        pen += fmaxf(usage - 0.4f, 0.f);
    }
    out[(size_t)NTOK * Dd] = 0.05f * (g_entsum / (float)NTOK) + pen;
}

// ---------------- launch ----------------------------------------------------
extern "C" void kernel_launch(void* const* d_in, const int* in_sizes, int n_in,
                              void* d_out, int out_size)
{
    (void)in_sizes; (void)n_in;
    const float* x    = (const float*)d_in[0];
    const float* Wq   = (const float*)d_in[1];
    const float* bq   = (const float*)d_in[2];
    const float* Wk   = (const float*)d_in[3];
    const float* bk   = (const float*)d_in[4];
    const float* Wv   = (const float*)d_in[5];
    const float* bv   = (const float*)d_in[6];
    const float* Wo   = (const float*)d_in[7];
    const float* bo   = (const float*)d_in[8];
    const float* ln1g = (const float*)d_in[9];
    const float* ln1b = (const float*)d_in[10];
    const float* ln2g = (const float*)d_in[11];
    const float* ln2b = (const float*)d_in[12];
    const float* Wg   = (const float*)d_in[13];
    const float* bg   = (const float*)d_in[14];
    const float* We   = (const float*)d_in[15];
    const float* be   = (const float*)d_in[16];
    float* out = (float*)d_out;

    float *p_ln1, *p_q, *p_k, *p_v, *p_o, *p_ln2;
    cudaGetSymbolAddress((void**)&p_ln1, g_ln1);
    cudaGetSymbolAddress((void**)&p_q,   g_qb);
    cudaGetSymbolAddress((void**)&p_k,   g_kb);
    cudaGetSymbolAddress((void**)&p_v,   g_vb);
    cudaGetSymbolAddress((void**)&p_o,   g_ob);
    cudaGetSymbolAddress((void**)&p_ln2, g_ln2);

    init_kernel<<<1, 32>>>();
    ln_kernel<<<NTOK, 256>>>(x, ln1g, ln1b, p_ln1);

    // QKV projections — only rows < 2176 per batch are ever consumed (17 tiles)
    for (int b = 0; b < Bb; b++) {
        const float* Ab = p_ln1 + (size_t)b * Ls * Dd;
        sgemm_bias<<<dim3(8, QROWS / 128), 256>>>(
            Ab, Wq, bq, nullptr, p_q + (size_t)b * Ls * Dd, Dd, Dd);
        sgemm_bias<<<dim3(1, QROWS / 128), 256>>>(
            Ab, Wk, bk, nullptr, p_k + (size_t)b * Ls * KVd, KVd, Dd);
        sgemm_bias<<<dim3(1, QROWS / 128), 256>>>(
            Ab, Wv, bv, nullptr, p_v + (size_t)b * Ls * KVd, KVd, Dd);
    }

    const int attn_smem = 2 * WINs * HDd * sizeof(float);  // 128 KB
    cudaFuncSetAttribute(attn_kernel,
                         cudaFuncAttributeMaxDynamicSharedMemorySize, attn_smem);
    attn_kernel<<<dim3(16, Hh, Bb), 256, attn_smem>>>(p_q, p_k, p_v, p_o);

    // h = x + O @ Wo + bo   (written straight into d_out)
    sgemm_bias<<<dim3(8, NTOK / 128), 256>>>(p_o, Wo, bo, x, out, Dd, Dd);

    ln_kernel<<<NTOK, 256>>>(out, ln2g, ln2b, p_ln2);
    gate_kernel<<<NTOK * 32 / 256, 256>>>(p_ln2, Wg, bg);
    moe_gemm<<<dim3(HIDs / 128, NTOK / 128, Ee), 256>>>(p_ln2, We, be, out);

    if (out_size > NTOK * Dd) fin_kernel<<<1, 1>>>(out);
}

// round 6
// speedup vs baseline: 3.2646x; 3.2646x over previous
#include <cuda_runtime.h>
#include <cuda_bf16.h>
#include <math.h>
#include <stdint.h>

#define Dd   1024
#define Ls   4096
#define NTOK 8192
#define HDd  64
#define WINs 256
#define Gg   2
#define Hh   16
#define Ee   8
#define HIDs 1024
#define QKVW 1280      // 1024 q + 128 k + 128 v
#define STRD 40        // padded bf16 row stride in smem tiles

typedef __nv_bfloat16 bf;
typedef __nv_bfloat162 bf2;

// ---------------- device scratch --------------------------------------------
__device__ float g_qkv[NTOK * QKVW];                 // fused q|k|v fp32
__device__ bf    g_ah[NTOK * Dd], g_al[NTOK * Dd];   // ln1 hi/lo
__device__ bf    g_oh[NTOK * Dd], g_ol[NTOK * Dd];   // attn out hi/lo
__device__ float g_ln2[NTOK * Dd];
__device__ bf    g_2h[NTOK * Dd], g_2l[NTOK * Dd];   // ln2 hi/lo
__device__ bf    g_wh[QKVW * Dd], g_wl[QKVW * Dd];   // [Wq;Wk;Wv]^T hi/lo
__device__ bf    g_woh[Dd * Dd],  g_wol[Dd * Dd];
__device__ bf    g_weh[Ee * HIDs * Dd], g_wel[Ee * HIDs * Dd];
__device__ float g_bqkv[QKVW];
__device__ float g_part[2 * NTOK * HIDs];
__device__ int   g_cnt[Ee];
__device__ int   g_list[Ee][NTOK];
__device__ float g_wl2[Ee][NTOK];
__device__ float g_entsum;

// ---------------- helpers ---------------------------------------------------
__device__ __forceinline__ uint32_t s2u(const void* p) {
    uint32_t a;
    asm("{ .reg .u64 t; cvta.to.shared.u64 t, %1; cvt.u32.u64 %0, t; }"
        : "=r"(a) : "l"(p));
    return a;
}
__device__ __forceinline__ void ldsm4(uint32_t* r, uint32_t addr) {
    asm volatile("ldmatrix.sync.aligned.m8n8.x4.shared.b16 {%0,%1,%2,%3}, [%4];"
                 : "=r"(r[0]), "=r"(r[1]), "=r"(r[2]), "=r"(r[3]) : "r"(addr));
}
__device__ __forceinline__ void ldsm2(uint32_t* r, uint32_t addr) {
    asm volatile("ldmatrix.sync.aligned.m8n8.x2.shared.b16 {%0,%1}, [%2];"
                 : "=r"(r[0]), "=r"(r[1]) : "r"(addr));
}
__device__ __forceinline__ void mma16816(float* c, const uint32_t* a, const uint32_t* b) {
    asm volatile(
        "mma.sync.aligned.m16n8k16.row.col.f32.bf16.bf16.f32 "
        "{%0,%1,%2,%3}, {%4,%5,%6,%7}, {%8,%9}, {%0,%1,%2,%3};"
        : "+f"(c[0]), "+f"(c[1]), "+f"(c[2]), "+f"(c[3])
        : "r"(a[0]), "r"(a[1]), "r"(a[2]), "r"(a[3]), "r"(b[0]), "r"(b[1]));
}
__device__ __forceinline__ void cpa16(uint32_t dst, const void* src) {
    asm volatile("cp.async.cg.shared.global [%0], [%1], 16;" :: "r"(dst), "l"(src));
}

// ---------------- init ------------------------------------------------------
__global__ void init_kernel() {
    int t = threadIdx.x;
    if (t < Ee) g_cnt[t] = 0;
    if (t == 0) g_entsum = 0.f;
}

__global__ void catb_kernel(const float* bq, const float* bk, const float* bv) {
    int i = blockIdx.x * 256 + threadIdx.x;
    if (i < 1024) g_bqkv[i] = bq[i];
    else if (i < 1152) g_bqkv[i] = bk[i - 1024];
    else if (i < 1280) g_bqkv[i] = bv[i - 1152];
}

// ---------------- layernorm with hi/lo emit ---------------------------------
__device__ __forceinline__ float brsum(float v, float* sh) {
    int lane = threadIdx.x & 31, w = threadIdx.x >> 5;
    #pragma unroll
    for (int o = 16; o; o >>= 1) v += __shfl_xor_sync(0xffffffffu, v, o);
    if (lane == 0) sh[w] = v;
    __syncthreads();
    if (w == 0) {
        float r = (lane < 8) ? sh[lane] : 0.f;
        #pragma unroll
        for (int o = 4; o; o >>= 1) r += __shfl_xor_sync(0xffffffffu, r, o);
        if (lane == 0) sh[0] = r;
    }
    __syncthreads();
    float r = sh[0];
    __syncthreads();
    return r;
}

__global__ __launch_bounds__(256) void ln_kernel(
    const float* __restrict__ x, const float* __restrict__ g,
    const float* __restrict__ b, float* __restrict__ outf,
    bf* __restrict__ oh, bf* __restrict__ ol)
{
    __shared__ float sh[8];
    size_t row = blockIdx.x;
    int tid = threadIdx.x;
    float4 v = ((const float4*)(x + row * Dd))[tid];
    float mean = brsum(v.x + v.y + v.z + v.w, sh) * (1.f / Dd);
    float d0 = v.x - mean, d1 = v.y - mean, d2 = v.z - mean, d3 = v.w - mean;
    float var = brsum(d0*d0 + d1*d1 + d2*d2 + d3*d3, sh) * (1.f / Dd);
    float inv = rsqrtf(var + 1e-5f);
    float4 gv = ((const float4*)g)[tid];
    float4 bv = ((const float4*)b)[tid];
    float o0 = d0*inv*gv.x + bv.x, o1 = d1*inv*gv.y + bv.y;
    float o2 = d2*inv*gv.z + bv.z, o3 = d3*inv*gv.w + bv.w;
    if (outf) ((float4*)(outf + row * Dd))[tid] = make_float4(o0, o1, o2, o3);
    bf h0 = __float2bfloat16(o0), h1 = __float2bfloat16(o1);
    bf h2 = __float2bfloat16(o2), h3 = __float2bfloat16(o3);
    bf2* hp = (bf2*)(oh + row * Dd);
    hp[2*tid]   = __halves2bfloat162(h0, h1);
    hp[2*tid+1] = __halves2bfloat162(h2, h3);
    bf2* lp = (bf2*)(ol + row * Dd);
    lp[2*tid]   = __halves2bfloat162(__float2bfloat16(o0 - __bfloat162float(h0)),
                                     __float2bfloat16(o1 - __bfloat162float(h1)));
    lp[2*tid+1] = __halves2bfloat162(__float2bfloat16(o2 - __bfloat162float(h2)),
                                     __float2bfloat16(o3 - __bfloat162float(h3)));
}

// ---------------- weight transpose + split: W[K,N] -> Wt[N,K] hi/lo ---------
__global__ __launch_bounds__(256) void tconv(
    const float* __restrict__ W, bf* __restrict__ Th, bf* __restrict__ Tl,
    int Kr, int Nc, size_t zW, size_t zT)
{
    __shared__ float t[32][33];
    const float* Wz = W + blockIdx.z * zW;
    bf* Thz = Th + blockIdx.z * zT;
    bf* Tlz = Tl + blockIdx.z * zT;
    int k0 = blockIdx.y * 32, n0 = blockIdx.x * 32;
    int tx = threadIdx.x & 31, ty = threadIdx.x >> 5;
    #pragma unroll
    for (int r = 0; r < 4; r++)
        t[ty + 8*r][tx] = Wz[(size_t)(k0 + ty + 8*r) * Nc + n0 + tx];
    __syncthreads();
    #pragma unroll
    for (int r = 0; r < 4; r++) {
        float v = t[tx][ty + 8*r];
        size_t o = (size_t)(n0 + ty + 8*r) * Kr + k0 + tx;
        bf h = __float2bfloat16(v);
        Thz[o] = h;
        Tlz[o] = __float2bfloat16(v - __bfloat162float(h));
    }
}

// ---------------- HMMA split-bf16 GEMM --------------------------------------
// C[m,n] = sum_k A[m,k]*Wt[n,k] + bias[n] (+res). K = 1024 always.
// mode 0: row0 = z*zRow + y*128, output fp32 C (ldc). mode 1: MoE gather/scatter.
// smem: 2 stages x {Ah,Al,Bh,Bl}[128][STRD] bf16  (stage = 40960 B)
__global__ __launch_bounds__(256, 1) void gemm_mma(
    const bf* __restrict__ Ahi, const bf* __restrict__ Alo,
    const bf* __restrict__ Bhi, const bf* __restrict__ Blo,
    const float* __restrict__ bias, const float* __restrict__ res,
    float* __restrict__ C, int zRow, int ldc, int mode)
{
    extern __shared__ bf sm[];
    __shared__ int s_ent[128];
    __shared__ float s_w[128];
    __shared__ int s_ridx[128];

    int tid = threadIdx.x, lane = tid & 31, wid = tid >> 5;
    int n0 = blockIdx.x * 128;
    int row0 = 0, cnt = 0, m0 = 0;
    const bf *bh = Bhi, *bl = Blo;
    const float* bptr = bias;
    if (mode == 1) {
        int e = blockIdx.z;
        cnt = g_cnt[e];
        m0 = blockIdx.y * 128;
        if (m0 >= cnt) return;
        bh = Bhi + ((size_t)e << 20);
        bl = Blo + ((size_t)e << 20);
        bptr = bias + e * HIDs;
        if (tid < 128) {
            int m = m0 + tid;
            int ent = (m < cnt) ? g_list[e][m] : -1;
            s_ent[tid] = ent;
            s_ridx[tid] = (ent >= 0) ? (ent >> 1) : -1;
            s_w[tid] = (m < cnt) ? g_wl2[e][m] : 0.f;
        }
        __syncthreads();
    } else {
        row0 = blockIdx.z * zRow + blockIdx.y * 128;
    }
    const int* rp = (mode == 1) ? s_ridx : nullptr;
    uint32_t sb = s2u(sm);

    float c[4][4][4] = {};
    int wm = (wid & 1) * 64, wn = (wid >> 1) * 32;

    // ---- loader ----
    #define LOAD_STAGE(s, k0)                                                   \
    do {                                                                        \
        for (int i = tid; i < 2048; i += 256) {                                 \
            int part = i >> 9, r = (i >> 2) & 127, cb = (i & 3) * 8;            \
            uint32_t dst = sb + (s) * 40960 + part * 10240 + (r * STRD + cb) * 2;\
            if (part < 2) {                                                     \
                int grow = rp ? rp[r] : (row0 + r);                             \
                if (grow < 0) continue;                                         \
                cpa16(dst, (part ? Alo : Ahi) + ((size_t)grow << 10) + (k0) + cb);\
            } else {                                                            \
                cpa16(dst, (part == 3 ? bl : bh) + ((size_t)(n0 + r) << 10) + (k0) + cb);\
            }                                                                   \
        }                                                                       \
        asm volatile("cp.async.commit_group;");                                 \
    } while (0)

    LOAD_STAGE(0, 0);

    for (int cc = 0; cc < 32; cc++) {
        if (cc < 31) LOAD_STAGE((cc + 1) & 1, (cc + 1) * 32);
        if (cc < 31) asm volatile("cp.async.wait_group 1;");
        else         asm volatile("cp.async.wait_group 0;");
        __syncthreads();

        uint32_t base = sb + (cc & 1) * 40960;
        #pragma unroll
        for (int ka = 0; ka < 2; ka++) {
            uint32_t a_h[4][4], a_l[4][4], b_h[4][2], b_l[4][2];
            int arow = wm + (lane & 15);
            int acol = ka * 16 + (lane >> 4) * 8;
            #pragma unroll
            for (int im = 0; im < 4; im++) {
                uint32_t ad = base + ((arow + im * 16) * STRD + acol) * 2;
                ldsm4(a_h[im], ad);
                ldsm4(a_l[im], ad + 10240);
            }
            int brow = wn + (lane & 7);
            int bcol = ka * 16 + ((lane >> 3) & 1) * 8;
            #pragma unroll
            for (int in = 0; in < 4; in++) {
                uint32_t bd = base + 2 * 10240 + ((brow + in * 8) * STRD + bcol) * 2;
                ldsm2(b_h[in], bd);
                ldsm2(b_l[in], bd + 10240);
            }
            #pragma unroll
            for (int im = 0; im < 4; im++)
                #pragma unroll
                for (int in = 0; in < 4; in++) {
                    mma16816(c[im][in], a_h[im], b_h[in]);
                    mma16816(c[im][in], a_h[im], b_l[in]);
                    mma16816(c[im][in], a_l[im], b_h[in]);
                }
        }
        __syncthreads();
    }

    // ---- epilogue ----
    int crow = lane >> 2, ccol = (lane & 3) * 2;
    #pragma unroll
    for (int im = 0; im < 4; im++) {
        #pragma unroll
        for (int h2 = 0; h2 < 2; h2++) {
            int r = wm + im * 16 + crow + h2 * 8;
            if (mode == 0) {
                size_t m = (size_t)(row0 + r);
                #pragma unroll
                for (int in = 0; in < 4; in++) {
                    int n = n0 + wn + in * 8 + ccol;
                    float2 v;
                    v.x = c[im][in][h2*2+0] + bptr[n];
                    v.y = c[im][in][h2*2+1] + bptr[n+1];
                    if (res) {
                        float2 q = *(const float2*)&res[m * ldc + n];
                        v.x += q.x; v.y += q.y;
                    }
                    *(float2*)&C[m * ldc + n] = v;
                }
            } else if (m0 + r < cnt) {
                int ent = s_ent[r];
                int tok = ent >> 1, slot = ent & 1;
                float w = s_w[r];
                float* dst = g_part + (((size_t)slot * NTOK + tok) << 10);
                #pragma unroll
                for (int in = 0; in < 4; in++) {
                    int n = n0 + wn + in * 8 + ccol;
                    float2 v;
                    v.x = w * (c[im][in][h2*2+0] + bptr[n]);
                    v.y = w * (c[im][in][h2*2+1] + bptr[n+1]);
                    *(float2*)&dst[n] = v;
                }
            }
        }
    }
}

// ---------------- windowed GQA attention (fused QKV input, hi/lo out) -------
__global__ __launch_bounds__(256, 1) void attn_kernel(
    const float* __restrict__ QKV, bf* __restrict__ Oh, bf* __restrict__ Ol)
{
    extern __shared__ float smem[];
    float* Ks = smem;
    float* Vs = smem + WINs * HDd;
    int n = blockIdx.x, h = blockIdx.y, b = blockIdx.z;
    int g = h & (Gg - 1);
    int kbase = n * (WINs / 2);
    const float* Kg = QKV + ((size_t)b * Ls + kbase) * QKVW + 1024 + g * HDd;
    const float* Vg = QKV + ((size_t)b * Ls + kbase) * QKVW + 1152 + g * HDd;
    for (int i = threadIdx.x; i < WINs * HDd / 4; i += 256) {
        int r = i >> 4, c = (i & 15) * 4;
        *(float4*)&Ks[r * HDd + c] = *(const float4*)&Kg[(size_t)r * QKVW + c];
        *(float4*)&Vs[r * HDd + c] = *(const float4*)&Vg[(size_t)r * QKVW + c];
    }
    __syncthreads();
    int w = threadIdx.x;
    const float* qr = QKV + ((size_t)b * Ls + kbase + w) * QKVW + h * HDd;
    float q[HDd], acc[HDd];
    #pragma unroll
    for (int i = 0; i < HDd; i++) { q[i] = qr[i] * 0.125f; acc[i] = 0.f; }
    float mrun = -1e30f, lrun = 0.f;
    for (int kc = 0; kc < WINs; kc += 8) {
        float s[8];
        #pragma unroll
        for (int j = 0; j < 8; j++) {
            const float* kr = &Ks[(kc + j) * HDd];
            float d = 0.f;
            #pragma unroll
            for (int i = 0; i < HDd; i++) d += q[i] * kr[i];
            s[j] = d;
        }
        float cm = s[0];
        #pragma unroll
        for (int j = 1; j < 8; j++) cm = fmaxf(cm, s[j]);
        float nm = fmaxf(mrun, cm);
        float sc = __expf(mrun - nm);
        lrun *= sc;
        #pragma unroll
        for (int i = 0; i < HDd; i++) acc[i] *= sc;
        #pragma unroll
        for (int j = 0; j < 8; j++) {
            float ev = __expf(s[j] - nm);
            lrun += ev;
            const float* vr = &Vs[(kc + j) * HDd];
            #pragma unroll
            for (int i = 0; i < HDd; i++) acc[i] += ev * vr[i];
        }
        mrun = nm;
    }
    float inv = 1.f / lrun;
    size_t ob = ((size_t)b * Ls + n * WINs + w) * Dd + h * HDd;
    #pragma unroll
    for (int i = 0; i < HDd; i += 2) {
        float v0 = acc[i] * inv, v1 = acc[i+1] * inv;
        bf h0 = __float2bfloat16(v0), h1 = __float2bfloat16(v1);
        *(bf2*)&Oh[ob + i] = __halves2bfloat162(h0, h1);
        *(bf2*)&Ol[ob + i] = __halves2bfloat162(
            __float2bfloat16(v0 - __bfloat162float(h0)),
            __float2bfloat16(v1 - __bfloat162float(h1)));
    }
}

// ---------------- gating ----------------------------------------------------
__global__ __launch_bounds__(256) void gate_kernel(
    const float* __restrict__ X, const float* __restrict__ Wg,
    const float* __restrict__ bg)
{
    int tok  = (blockIdx.x * 256 + threadIdx.x) >> 5;
    int lane = threadIdx.x & 31;
    if (tok >= NTOK) return;
    const float* xr = X + (size_t)tok * Dd;
    float a[Ee];
    #pragma unroll
    for (int e = 0; e < Ee; e++) a[e] = 0.f;
    for (int d = lane; d < Dd; d += 32) {
        float xv = xr[d];
        const float4* wr = (const float4*)&Wg[d * Ee];
        float4 w0 = wr[0], w1 = wr[1];
        a[0] += xv * w0.x; a[1] += xv * w0.y; a[2] += xv * w0.z; a[3] += xv * w0.w;
        a[4] += xv * w1.x; a[5] += xv * w1.y; a[6] += xv * w1.z; a[7] += xv * w1.w;
    }
    #pragma unroll
    for (int e = 0; e < Ee; e++)
        #pragma unroll
        for (int o = 16; o; o >>= 1) a[e] += __shfl_xor_sync(0xffffffffu, a[e], o);
    if (lane == 0) {
        float mx = -1e30f;
        #pragma unroll
        for (int e = 0; e < Ee; e++) { a[e] += bg[e]; mx = fmaxf(mx, a[e]); }
        float p[Ee], se = 0.f;
        #pragma unroll
        for (int e = 0; e < Ee; e++) { p[e] = __expf(a[e] - mx); se += p[e]; }
        float inv = 1.f / se, ent = 0.f;
        #pragma unroll
        for (int e = 0; e < Ee; e++) { p[e] *= inv; ent -= p[e] * logf(p[e] + 1e-8f); }
        atomicAdd(&g_entsum, ent);
        int i0 = 0;
        #pragma unroll
        for (int e = 1; e < Ee; e++) if (p[e] > p[i0]) i0 = e;
        int i1 = -1;
        #pragma unroll
        for (int e = 0; e < Ee; e++) {
            if (e == i0) continue;
            if (i1 < 0 || p[e] > p[i1]) i1 = e;
        }
        int p0 = atomicAdd(&g_cnt[i0], 1);
        g_list[i0][p0] = tok * 2;     g_wl2[i0][p0] = p[i0];
        int p1 = atomicAdd(&g_cnt[i1], 1);
        g_list[i1][p1] = tok * 2 + 1; g_wl2[i1][p1] = p[i1];
    }
}

// ---------------- fuse + aux ------------------------------------------------
__global__ __launch_bounds__(256) void fuse_kernel(float* __restrict__ out) {
    size_t i = (size_t)blockIdx.x * 256 + threadIdx.x;
    float4 a = ((const float4*)g_part)[i];
    float4 b = ((const float4*)(g_part + (size_t)NTOK * HIDs))[i];
    float4 o = ((float4*)out)[i];
    o.x += a.x + b.x; o.y += a.y + b.y; o.z += a.z + b.z; o.w += a.w + b.w;
    ((float4*)out)[i] = o;
}

__global__ void fin_kernel(float* __restrict__ out) {
    float pen = 0.f;
    #pragma unroll
    for (int e = 0; e < Ee; e++) {
        float usage = (float)g_cnt[e] / (8192.f + 1e-8f);
        pen += fmaxf(usage - 0.4f, 0.f);
    }
    out[(size_t)NTOK * Dd] = 0.05f * (g_entsum / (float)NTOK) + pen;
}

// ---------------- launch ----------------------------------------------------
extern "C" void kernel_launch(void* const* d_in, const int* in_sizes, int n_in,
                              void* d_out, int out_size)
{
    (void)in_sizes; (void)n_in;
    const float* x    = (const float*)d_in[0];
    const float* Wq   = (const float*)d_in[1];
    const float* bq   = (const float*)d_in[2];
    const float* Wk   = (const float*)d_in[3];
    const float* bk   = (const float*)d_in[4];
    const float* Wv   = (const float*)d_in[5];
    const float* bv   = (const float*)d_in[6];
    const float* Wo   = (const float*)d_in[7];
    const float* bo   = (const float*)d_in[8];
    const float* ln1g = (const float*)d_in[9];
    const float* ln1b = (const float*)d_in[10];
    const float* ln2g = (const float*)d_in[11];
    const float* ln2b = (const float*)d_in[12];
    const float* Wg   = (const float*)d_in[13];
    const float* bg   = (const float*)d_in[14];
    const float* We   = (const float*)d_in[15];
    const float* be   = (const float*)d_in[16];
    float* out = (float*)d_out;

    float *p_qkv, *p_ln2, *p_bqkv;
    bf *p_ah, *p_al, *p_oh, *p_ol, *p_2h, *p_2l;
    bf *p_wh, *p_wl, *p_woh, *p_wol, *p_weh, *p_wel;
    cudaGetSymbolAddress((void**)&p_qkv, g_qkv);
    cudaGetSymbolAddress((void**)&p_ln2, g_ln2);
    cudaGetSymbolAddress((void**)&p_bqkv, g_bqkv);
    cudaGetSymbolAddress((void**)&p_ah,  g_ah);
    cudaGetSymbolAddress((void**)&p_al,  g_al);
    cudaGetSymbolAddress((void**)&p_oh,  g_oh);
    cudaGetSymbolAddress((void**)&p_ol,  g_ol);
    cudaGetSymbolAddress((void**)&p_2h,  g_2h);
    cudaGetSymbolAddress((void**)&p_2l,  g_2l);
    cudaGetSymbolAddress((void**)&p_wh,  g_wh);
    cudaGetSymbolAddress((void**)&p_wl,  g_wl);
    cudaGetSymbolAddress((void**)&p_woh, g_woh);
    cudaGetSymbolAddress((void**)&p_wol, g_wol);
    cudaGetSymbolAddress((void**)&p_weh, g_weh);
    cudaGetSymbolAddress((void**)&p_wel, g_wel);

    const int GSMEM = 2 * 40960;  // 80 KB
    cudaFuncSetAttribute(gemm_mma, cudaFuncAttributeMaxDynamicSharedMemorySize, GSMEM);
    const int ASMEM = 2 * WINs * HDd * sizeof(float);  // 128 KB
    cudaFuncSetAttribute(attn_kernel, cudaFuncAttributeMaxDynamicSharedMemorySize, ASMEM);

    init_kernel<<<1, 32>>>();
    catb_kernel<<<5, 256>>>(bq, bk, bv);
    ln_kernel<<<NTOK, 256>>>(x, ln1g, ln1b, nullptr, p_ah, p_al);

    // weights: [Wq;Wk;Wv] transposed into g_wh/g_wl rows 0..1279
    tconv<<<dim3(32, 32), 256>>>(Wq, p_wh, p_wl, Dd, Dd, 0, 0);
    tconv<<<dim3(4, 32),  256>>>(Wk, p_wh + (size_t)1024 * Dd,
                                 p_wl + (size_t)1024 * Dd, Dd, 128, 0, 0);
    tconv<<<dim3(4, 32),  256>>>(Wv, p_wh + (size_t)1152 * Dd,
                                 p_wl + (size_t)1152 * Dd, Dd, 128, 0, 0);
    tconv<<<dim3(32, 32), 256>>>(Wo, p_woh, p_wol, Dd, Dd, 0, 0);
    tconv<<<dim3(32, 32, 8), 256>>>(We, p_weh, p_wel, Dd, HIDs,
                                    (size_t)Dd * HIDs, (size_t)Dd * HIDs);

    // fused QKV: rows < 2176 per batch (17 M-tiles), N = 1280 (10 tiles)
    gemm_mma<<<dim3(10, 17, 2), 256, GSMEM>>>(p_ah, p_al, p_wh, p_wl, p_bqkv,
                                              nullptr, p_qkv, Ls, QKVW, 0);

    attn_kernel<<<dim3(16, Hh, 2), 256, ASMEM>>>(p_qkv, p_oh, p_ol);

    // h = x + O @ Wo + bo -> d_out
    gemm_mma<<<dim3(8, 64, 1), 256, GSMEM>>>(p_oh, p_ol, p_woh, p_wol, bo,
                                             x, out, 0, Dd, 0);

    ln_kernel<<<NTOK, 256>>>(out, ln2g, ln2b, p_ln2, p_2h, p_2l);
    gate_kernel<<<NTOK * 32 / 256, 256>>>(p_ln2, Wg, bg);
    gemm_mma<<<dim3(8, 64, 8), 256, GSMEM>>>(p_2h, p_2l, p_weh, p_wel, be,
                                             nullptr, nullptr, 0, HIDs, 1);
    fuse_kernel<<<NTOK * HIDs / 1024, 256>>>(out);
    if (out_size > NTOK * Dd) fin_kernel<<<1, 1>>>(out);
}

// round 7
// speedup vs baseline: 3.3305x; 1.0202x over previous
#include <cuda_runtime.h>
#include <cuda_bf16.h>
#include <math.h>
#include <stdint.h>

#define Dd   1024
#define Ls   4096
#define NTOK 8192
#define HDd  64
#define WINs 256
#define Gg   2
#define Hh   16
#define Ee   8
#define HIDs 1024
#define QKVW 1280      // 1024 q + 128 k + 128 v
#define STRD 40        // padded bf16 row stride in smem tiles
#define STAGEB 40960   // bytes per pipeline stage

typedef __nv_bfloat16 bf;
typedef __nv_bfloat162 bf2;

// ---------------- device scratch --------------------------------------------
__device__ float g_qkv[NTOK * QKVW];                 // fused q|k|v fp32
__device__ bf    g_ah[NTOK * Dd], g_al[NTOK * Dd];   // ln1 hi/lo
__device__ bf    g_oh[NTOK * Dd], g_ol[NTOK * Dd];   // attn out hi/lo
__device__ float g_ln2[NTOK * Dd];
__device__ bf    g_2h[NTOK * Dd], g_2l[NTOK * Dd];   // ln2 hi/lo
__device__ bf    g_wh[QKVW * Dd], g_wl[QKVW * Dd];   // [Wq;Wk;Wv]^T hi/lo
__device__ bf    g_woh[Dd * Dd],  g_wol[Dd * Dd];
__device__ bf    g_weh[Ee * HIDs * Dd], g_wel[Ee * HIDs * Dd];
__device__ float g_bqkv[QKVW];
__device__ float g_part[2 * NTOK * HIDs];
__device__ int   g_cnt[Ee];
__device__ int   g_list[Ee][NTOK];
__device__ float g_wl2[Ee][NTOK];
__device__ float g_entsum;

// ---------------- helpers ---------------------------------------------------
__device__ __forceinline__ uint32_t s2u(const void* p) {
    uint32_t a;
    asm("{ .reg .u64 t; cvta.to.shared.u64 t, %1; cvt.u32.u64 %0, t; }"
        : "=r"(a) : "l"(p));
    return a;
}
__device__ __forceinline__ void ldsm4(uint32_t* r, uint32_t addr) {
    asm volatile("ldmatrix.sync.aligned.m8n8.x4.shared.b16 {%0,%1,%2,%3}, [%4];"
                 : "=r"(r[0]), "=r"(r[1]), "=r"(r[2]), "=r"(r[3]) : "r"(addr));
}
__device__ __forceinline__ void mma16816(float* c, const uint32_t* a, const uint32_t* b) {
    asm volatile(
        "mma.sync.aligned.m16n8k16.row.col.f32.bf16.bf16.f32 "
        "{%0,%1,%2,%3}, {%4,%5,%6,%7}, {%8,%9}, {%0,%1,%2,%3};"
        : "+f"(c[0]), "+f"(c[1]), "+f"(c[2]), "+f"(c[3])
        : "r"(a[0]), "r"(a[1]), "r"(a[2]), "r"(a[3]), "r"(b[0]), "r"(b[1]));
}
__device__ __forceinline__ void cpa16(uint32_t dst, const void* src) {
    asm volatile("cp.async.cg.shared.global [%0], [%1], 16;" :: "r"(dst), "l"(src));
}

// ---------------- init ------------------------------------------------------
__global__ void init_kernel() {
    int t = threadIdx.x;
    if (t < Ee) g_cnt[t] = 0;
    if (t == 0) g_entsum = 0.f;
}

__global__ void catb_kernel(const float* bq, const float* bk, const float* bv) {
    int i = blockIdx.x * 256 + threadIdx.x;
    if (i < 1024) g_bqkv[i] = bq[i];
    else if (i < 1152) g_bqkv[i] = bk[i - 1024];
    else if (i < 1280) g_bqkv[i] = bv[i - 1152];
}

// ---------------- layernorm with hi/lo emit ---------------------------------
__device__ __forceinline__ float brsum(float v, float* sh) {
    int lane = threadIdx.x & 31, w = threadIdx.x >> 5;
    #pragma unroll
    for (int o = 16; o; o >>= 1) v += __shfl_xor_sync(0xffffffffu, v, o);
    if (lane == 0) sh[w] = v;
    __syncthreads();
    if (w == 0) {
        float r = (lane < 8) ? sh[lane] : 0.f;
        #pragma unroll
        for (int o = 4; o; o >>= 1) r += __shfl_xor_sync(0xffffffffu, r, o);
        if (lane == 0) sh[0] = r;
    }
    __syncthreads();
    float r = sh[0];
    __syncthreads();
    return r;
}

__global__ __launch_bounds__(256) void ln_kernel(
    const float* __restrict__ x, const float* __restrict__ g,
    const float* __restrict__ b, float* __restrict__ outf,
    bf* __restrict__ oh, bf* __restrict__ ol)
{
    __shared__ float sh[8];
    size_t row = blockIdx.x;
    int tid = threadIdx.x;
    float4 v = ((const float4*)(x + row * Dd))[tid];
    float mean = brsum(v.x + v.y + v.z + v.w, sh) * (1.f / Dd);
    float d0 = v.x - mean, d1 = v.y - mean, d2 = v.z - mean, d3 = v.w - mean;
    float var = brsum(d0*d0 + d1*d1 + d2*d2 + d3*d3, sh) * (1.f / Dd);
    float inv = rsqrtf(var + 1e-5f);
    float4 gv = ((const float4*)g)[tid];
    float4 bv = ((const float4*)b)[tid];
    float o0 = d0*inv*gv.x + bv.x, o1 = d1*inv*gv.y + bv.y;
    float o2 = d2*inv*gv.z + bv.z, o3 = d3*inv*gv.w + bv.w;
    if (outf) ((float4*)(outf + row * Dd))[tid] = make_float4(o0, o1, o2, o3);
    bf h0 = __float2bfloat16(o0), h1 = __float2bfloat16(o1);
    bf h2 = __float2bfloat16(o2), h3 = __float2bfloat16(o3);
    bf2* hp = (bf2*)(oh + row * Dd);
    hp[2*tid]   = __halves2bfloat162(h0, h1);
    hp[2*tid+1] = __halves2bfloat162(h2, h3);
    bf2* lp = (bf2*)(ol + row * Dd);
    lp[2*tid]   = __halves2bfloat162(__float2bfloat16(o0 - __bfloat162float(h0)),
                                     __float2bfloat16(o1 - __bfloat162float(h1)));
    lp[2*tid+1] = __halves2bfloat162(__float2bfloat16(o2 - __bfloat162float(h2)),
                                     __float2bfloat16(o3 - __bfloat162float(h3)));
}

// ---------------- weight transpose + split: W[K,N] -> Wt[N,K] hi/lo ---------
__global__ __launch_bounds__(256) void tconv(
    const float* __restrict__ W, bf* __restrict__ Th, bf* __restrict__ Tl,
    int Kr, int Nc, size_t zW, size_t zT)
{
    __shared__ float t[32][33];
    const float* Wz = W + blockIdx.z * zW;
    bf* Thz = Th + blockIdx.z * zT;
    bf* Tlz = Tl + blockIdx.z * zT;
    int k0 = blockIdx.y * 32, n0 = blockIdx.x * 32;
    int tx = threadIdx.x & 31, ty = threadIdx.x >> 5;
    #pragma unroll
    for (int r = 0; r < 4; r++)
        t[ty + 8*r][tx] = Wz[(size_t)(k0 + ty + 8*r) * Nc + n0 + tx];
    __syncthreads();
    #pragma unroll
    for (int r = 0; r < 4; r++) {
        float v = t[tx][ty + 8*r];
        size_t o = (size_t)(n0 + ty + 8*r) * Kr + k0 + tx;
        bf h = __float2bfloat16(v);
        Thz[o] = h;
        Tlz[o] = __float2bfloat16(v - __bfloat162float(h));
    }
}

// ---------------- HMMA split-bf16 GEMM, 4-stage cp.async pipeline -----------
// C[m,n] = sum_k A[m,k]*Wt[n,k] + bias[n] (+res). K = 1024 always.
// mode 0: row0 = z*zRow + y*128, output fp32 C (ldc). mode 1: MoE gather/scatter.
// smem: 4 stages x {Ah,Al,Bh,Bl}[128][STRD] bf16  (stage = 40960 B)
__global__ __launch_bounds__(256, 1) void gemm_mma(
    const bf* __restrict__ Ahi, const bf* __restrict__ Alo,
    const bf* __restrict__ Bhi, const bf* __restrict__ Blo,
    const float* __restrict__ bias, const float* __restrict__ res,
    float* __restrict__ C, int zRow, int ldc, int mode)
{
    extern __shared__ bf sm[];
    __shared__ int s_ent[128];
    __shared__ float s_w[128];
    __shared__ int s_ridx[128];

    int tid = threadIdx.x, lane = tid & 31, wid = tid >> 5;
    int n0 = blockIdx.x * 128;
    int row0 = 0, cnt = 0, m0 = 0;
    const bf *bh = Bhi, *bl = Blo;
    const float* bptr = bias;
    if (mode == 1) {
        int e = blockIdx.z;
        cnt = g_cnt[e];
        m0 = blockIdx.y * 128;
        if (m0 >= cnt) return;
        bh = Bhi + ((size_t)e << 20);
        bl = Blo + ((size_t)e << 20);
        bptr = bias + e * HIDs;
        if (tid < 128) {
            int m = m0 + tid;
            int ent = (m < cnt) ? g_list[e][m] : -1;
            s_ent[tid] = ent;
            s_ridx[tid] = (ent >= 0) ? (ent >> 1) : -1;
            s_w[tid] = (m < cnt) ? g_wl2[e][m] : 0.f;
        }
        __syncthreads();
    } else {
        row0 = blockIdx.z * zRow + blockIdx.y * 128;
    }
    const int* rp = (mode == 1) ? s_ridx : nullptr;
    uint32_t sb = s2u(sm);

    float c[4][4][4] = {};
    int wm = (wid & 1) * 64, wn = (wid >> 1) * 32;

    #define LOAD_STAGE(s, k0)                                                   \
    do {                                                                        \
        for (int i = tid; i < 2048; i += 256) {                                 \
            int part = i >> 9, r = (i >> 2) & 127, cb = (i & 3) * 8;            \
            uint32_t dst = sb + (s) * STAGEB + part * 10240 + (r * STRD + cb) * 2;\
            if (part < 2) {                                                     \
                int grow = rp ? rp[r] : (row0 + r);                             \
                if (grow < 0) continue;                                         \
                cpa16(dst, (part ? Alo : Ahi) + ((size_t)grow << 10) + (k0) + cb);\
            } else {                                                            \
                cpa16(dst, (part == 3 ? bl : bh) + ((size_t)(n0 + r) << 10) + (k0) + cb);\
            }                                                                   \
        }                                                                       \
        asm volatile("cp.async.commit_group;");                                 \
    } while (0)

    LOAD_STAGE(0, 0);
    LOAD_STAGE(1, 32);
    LOAD_STAGE(2, 64);

    for (int cc = 0; cc < 32; cc++) {
        asm volatile("cp.async.wait_group 2;");   // stage cc complete
        __syncthreads();                          // visibility + WAR for ring reuse
        if (cc < 29) LOAD_STAGE((cc + 3) & 3, (cc + 3) * 32);
        else         asm volatile("cp.async.commit_group;");  // keep group count uniform

        uint32_t base = sb + (cc & 3) * STAGEB;
        #pragma unroll
        for (int ka = 0; ka < 2; ka++) {
            uint32_t a_h[4][4], a_l[4][4], b_h[4][2], b_l[4][2];
            int arow = wm + (lane & 15);
            int acol = ka * 16 + (lane >> 4) * 8;
            #pragma unroll
            for (int im = 0; im < 4; im++) {
                uint32_t ad = base + ((arow + im * 16) * STRD + acol) * 2;
                ldsm4(a_h[im], ad);
                ldsm4(a_l[im], ad + 10240);
            }
            // B: one ldsm4 covers two n8 tiles (matrices: [tilePair][khalf])
            int mtx = lane >> 3;
            int brow_off = (mtx >> 1) * 8 + (lane & 7);
            int bcol = ka * 16 + (mtx & 1) * 8;
            #pragma unroll
            for (int inb = 0; inb < 4; inb += 2) {
                uint32_t bd = base + 2 * 10240 +
                              ((wn + inb * 8 + brow_off) * STRD + bcol) * 2;
                uint32_t t4[4];
                ldsm4(t4, bd);
                b_h[inb][0] = t4[0]; b_h[inb][1] = t4[1];
                b_h[inb+1][0] = t4[2]; b_h[inb+1][1] = t4[3];
                ldsm4(t4, bd + 10240);
                b_l[inb][0] = t4[0]; b_l[inb][1] = t4[1];
                b_l[inb+1][0] = t4[2]; b_l[inb+1][1] = t4[3];
            }
            #pragma unroll
            for (int im = 0; im < 4; im++)
                #pragma unroll
                for (int in = 0; in < 4; in++) {
                    mma16816(c[im][in], a_h[im], b_h[in]);
                    mma16816(c[im][in], a_h[im], b_l[in]);
                    mma16816(c[im][in], a_l[im], b_h[in]);
                }
        }
    }

    // ---- epilogue ----
    int crow = lane >> 2, ccol = (lane & 3) * 2;
    #pragma unroll
    for (int im = 0; im < 4; im++) {
        #pragma unroll
        for (int h2 = 0; h2 < 2; h2++) {
            int r = wm + im * 16 + crow + h2 * 8;
            if (mode == 0) {
                size_t m = (size_t)(row0 + r);
                #pragma unroll
                for (int in = 0; in < 4; in++) {
                    int n = n0 + wn + in * 8 + ccol;
                    float2 v;
                    v.x = c[im][in][h2*2+0] + bptr[n];
                    v.y = c[im][in][h2*2+1] + bptr[n+1];
                    if (res) {
                        float2 q = *(const float2*)&res[m * ldc + n];
                        v.x += q.x; v.y += q.y;
                    }
                    *(float2*)&C[m * ldc + n] = v;
                }
            } else if (m0 + r < cnt) {
                int ent = s_ent[r];
                int tok = ent >> 1, slot = ent & 1;
                float w = s_w[r];
                float* dst = g_part + (((size_t)slot * NTOK + tok) << 10);
                #pragma unroll
                for (int in = 0; in < 4; in++) {
                    int n = n0 + wn + in * 8 + ccol;
                    float2 v;
                    v.x = w * (c[im][in][h2*2+0] + bptr[n]);
                    v.y = w * (c[im][in][h2*2+1] + bptr[n+1]);
                    *(float2*)&dst[n] = v;
                }
            }
        }
    }
}

// ---------------- windowed GQA attention (fused QKV input, hi/lo out) -------
__global__ __launch_bounds__(256, 1) void attn_kernel(
    const float* __restrict__ QKV, bf* __restrict__ Oh, bf* __restrict__ Ol)
{
    extern __shared__ float smem[];
    float* Ks = smem;
    float* Vs = smem + WINs * HDd;
    int n = blockIdx.x, h = blockIdx.y, b = blockIdx.z;
    int g = h & (Gg - 1);
    int kbase = n * (WINs / 2);
    const float* Kg = QKV + ((size_t)b * Ls + kbase) * QKVW + 1024 + g * HDd;
    const float* Vg = QKV + ((size_t)b * Ls + kbase) * QKVW + 1152 + g * HDd;
    for (int i = threadIdx.x; i < WINs * HDd / 4; i += 256) {
        int r = i >> 4, c = (i & 15) * 4;
        *(float4*)&Ks[r * HDd + c] = *(const float4*)&Kg[(size_t)r * QKVW + c];
        *(float4*)&Vs[r * HDd + c] = *(const float4*)&Vg[(size_t)r * QKVW + c];
    }
    __syncthreads();
    int w = threadIdx.x;
    const float* qr = QKV + ((size_t)b * Ls + kbase + w) * QKVW + h * HDd;
    float q[HDd], acc[HDd];
    #pragma unroll
    for (int i = 0; i < HDd; i++) { q[i] = qr[i] * 0.125f; acc[i] = 0.f; }
    float mrun = -1e30f, lrun = 0.f;
    for (int kc = 0; kc < WINs; kc += 8) {
        float s[8];
        #pragma unroll
        for (int j = 0; j < 8; j++) {
            const float* kr = &Ks[(kc + j) * HDd];
            float d = 0.f;
            #pragma unroll
            for (int i = 0; i < HDd; i++) d += q[i] * kr[i];
            s[j] = d;
        }
        float cm = s[0];
        #pragma unroll
        for (int j = 1; j < 8; j++) cm = fmaxf(cm, s[j]);
        float nm = fmaxf(mrun, cm);
        float sc = __expf(mrun - nm);
        lrun *= sc;
        #pragma unroll
        for (int i = 0; i < HDd; i++) acc[i] *= sc;
        #pragma unroll
        for (int j = 0; j < 8; j++) {
            float ev = __expf(s[j] - nm);
            lrun += ev;
            const float* vr = &Vs[(kc + j) * HDd];
            #pragma unroll
            for (int i = 0; i < HDd; i++) acc[i] += ev * vr[i];
        }
        mrun = nm;
    }
    float inv = 1.f / lrun;
    size_t ob = ((size_t)b * Ls + n * WINs + w) * Dd + h * HDd;
    #pragma unroll
    for (int i = 0; i < HDd; i += 2) {
        float v0 = acc[i] * inv, v1 = acc[i+1] * inv;
        bf h0 = __float2bfloat16(v0), h1 = __float2bfloat16(v1);
        *(bf2*)&Oh[ob + i] = __halves2bfloat162(h0, h1);
        *(bf2*)&Ol[ob + i] = __halves2bfloat162(
            __float2bfloat16(v0 - __bfloat162float(h0)),
            __float2bfloat16(v1 - __bfloat162float(h1)));
    }
}

// ---------------- gating ----------------------------------------------------
__global__ __launch_bounds__(256) void gate_kernel(
    const float* __restrict__ X, const float* __restrict__ Wg,
    const float* __restrict__ bg)
{
    int tok  = (blockIdx.x * 256 + threadIdx.x) >> 5;
    int lane = threadIdx.x & 31;
    if (tok >= NTOK) return;
    const float* xr = X + (size_t)tok * Dd;
    float a[Ee];
    #pragma unroll
    for (int e = 0; e < Ee; e++) a[e] = 0.f;
    for (int d = lane; d < Dd; d += 32) {
        float xv = xr[d];
        const float4* wr = (const float4*)&Wg[d * Ee];
        float4 w0 = wr[0], w1 = wr[1];
        a[0] += xv * w0.x; a[1] += xv * w0.y; a[2] += xv * w0.z; a[3] += xv * w0.w;
        a[4] += xv * w1.x; a[5] += xv * w1.y; a[6] += xv * w1.z; a[7] += xv * w1.w;
    }
    #pragma unroll
    for (int e = 0; e < Ee; e++)
        #pragma unroll
        for (int o = 16; o; o >>= 1) a[e] += __shfl_xor_sync(0xffffffffu, a[e], o);
    if (lane == 0) {
        float mx = -1e30f;
        #pragma unroll
        for (int e = 0; e < Ee; e++) { a[e] += bg[e]; mx = fmaxf(mx, a[e]); }
        float p[Ee], se = 0.f;
        #pragma unroll
        for (int e = 0; e < Ee; e++) { p[e] = __expf(a[e] - mx); se += p[e]; }
        float inv = 1.f / se, ent = 0.f;
        #pragma unroll
        for (int e = 0; e < Ee; e++) { p[e] *= inv; ent -= p[e] * logf(p[e] + 1e-8f); }
        atomicAdd(&g_entsum, ent);
        int i0 = 0;
        #pragma unroll
        for (int e = 1; e < Ee; e++) if (p[e] > p[i0]) i0 = e;
        int i1 = -1;
        #pragma unroll
        for (int e = 0; e < Ee; e++) {
            if (e == i0) continue;
            if (i1 < 0 || p[e] > p[i1]) i1 = e;
        }
        int p0 = atomicAdd(&g_cnt[i0], 1);
        g_list[i0][p0] = tok * 2;     g_wl2[i0][p0] = p[i0];
        int p1 = atomicAdd(&g_cnt[i1], 1);
        g_list[i1][p1] = tok * 2 + 1; g_wl2[i1][p1] = p[i1];
    }
}

// ---------------- fuse + aux ------------------------------------------------
__global__ __launch_bounds__(256) void fuse_kernel(float* __restrict__ out) {
    size_t i = (size_t)blockIdx.x * 256 + threadIdx.x;
    float4 a = ((const float4*)g_part)[i];
    float4 b = ((const float4*)(g_part + (size_t)NTOK * HIDs))[i];
    float4 o = ((float4*)out)[i];
    o.x += a.x + b.x; o.y += a.y + b.y; o.z += a.z + b.z; o.w += a.w + b.w;
    ((float4*)out)[i] = o;
}

__global__ void fin_kernel(float* __restrict__ out) {
    float pen = 0.f;
    #pragma unroll
    for (int e = 0; e < Ee; e++) {
        float usage = (float)g_cnt[e] / (8192.f + 1e-8f);
        pen += fmaxf(usage - 0.4f, 0.f);
    }
    out[(size_t)NTOK * Dd] = 0.05f * (g_entsum / (float)NTOK) + pen;
}

// ---------------- launch ----------------------------------------------------
extern "C" void kernel_launch(void* const* d_in, const int* in_sizes, int n_in,
                              void* d_out, int out_size)
{
    (void)in_sizes; (void)n_in;
    const float* x    = (const float*)d_in[0];
    const float* Wq   = (const float*)d_in[1];
    const float* bq   = (const float*)d_in[2];
    const float* Wk   = (const float*)d_in[3];
    const float* bk   = (const float*)d_in[4];
    const float* Wv   = (const float*)d_in[5];
    const float* bv   = (const float*)d_in[6];
    const float* Wo   = (const float*)d_in[7];
    const float* bo   = (const float*)d_in[8];
    const float* ln1g = (const float*)d_in[9];
    const float* ln1b = (const float*)d_in[10];
    const float* ln2g = (const float*)d_in[11];
    const float* ln2b = (const float*)d_in[12];
    const float* Wg   = (const float*)d_in[13];
    const float* bg   = (const float*)d_in[14];
    const float* We   = (const float*)d_in[15];
    const float* be   = (const float*)d_in[16];
    float* out = (float*)d_out;

    float *p_qkv, *p_ln2, *p_bqkv;
    bf *p_ah, *p_al, *p_oh, *p_ol, *p_2h, *p_2l;
    bf *p_wh, *p_wl, *p_woh, *p_wol, *p_weh, *p_wel;
    cudaGetSymbolAddress((void**)&p_qkv, g_qkv);
    cudaGetSymbolAddress((void**)&p_ln2, g_ln2);
    cudaGetSymbolAddress((void**)&p_bqkv, g_bqkv);
    cudaGetSymbolAddress((void**)&p_ah,  g_ah);
    cudaGetSymbolAddress((void**)&p_al,  g_al);
    cudaGetSymbolAddress((void**)&p_oh,  g_oh);
    cudaGetSymbolAddress((void**)&p_ol,  g_ol);
    cudaGetSymbolAddress((void**)&p_2h,  g_2h);
    cudaGetSymbolAddress((void**)&p_2l,  g_2l);
    cudaGetSymbolAddress((void**)&p_wh,  g_wh);
    cudaGetSymbolAddress((void**)&p_wl,  g_wl);
    cudaGetSymbolAddress((void**)&p_woh, g_woh);
    cudaGetSymbolAddress((void**)&p_wol, g_wol);
    cudaGetSymbolAddress((void**)&p_weh, g_weh);
    cudaGetSymbolAddress((void**)&p_wel, g_wel);

    const int GSMEM = 4 * STAGEB;  // 160 KB
    cudaFuncSetAttribute(gemm_mma, cudaFuncAttributeMaxDynamicSharedMemorySize, GSMEM);
    const int ASMEM = 2 * WINs * HDd * sizeof(float);  // 128 KB
    cudaFuncSetAttribute(attn_kernel, cudaFuncAttributeMaxDynamicSharedMemorySize, ASMEM);

    init_kernel<<<1, 32>>>();
    catb_kernel<<<5, 256>>>(bq, bk, bv);
    ln_kernel<<<NTOK, 256>>>(x, ln1g, ln1b, nullptr, p_ah, p_al);

    // weights: [Wq;Wk;Wv] transposed into g_wh/g_wl rows 0..1279
    tconv<<<dim3(32, 32), 256>>>(Wq, p_wh, p_wl, Dd, Dd, 0, 0);
    tconv<<<dim3(4, 32),  256>>>(Wk, p_wh + (size_t)1024 * Dd,
                                 p_wl + (size_t)1024 * Dd, Dd, 128, 0, 0);
    tconv<<<dim3(4, 32),  256>>>(Wv, p_wh + (size_t)1152 * Dd,
                                 p_wl + (size_t)1152 * Dd, Dd, 128, 0, 0);
    tconv<<<dim3(32, 32), 256>>>(Wo, p_woh, p_wol, Dd, Dd, 0, 0);
    tconv<<<dim3(32, 32, 8), 256>>>(We, p_weh, p_wel, Dd, HIDs,
                                    (size_t)Dd * HIDs, (size_t)Dd * HIDs);

    // fused QKV: rows < 2176 per batch (17 M-tiles), N = 1280 (10 tiles)
    gemm_mma<<<dim3(10, 17, 2), 256, GSMEM>>>(p_ah, p_al, p_wh, p_wl, p_bqkv,
                                              nullptr, p_qkv, Ls, QKVW, 0);

    attn_kernel<<<dim3(16, Hh, 2), 256, ASMEM>>>(p_qkv, p_oh, p_ol);

    // h = x + O @ Wo + bo -> d_out
    gemm_mma<<<dim3(8, 64, 1), 256, GSMEM>>>(p_oh, p_ol, p_woh, p_wol, bo,
                                             x, out, 0, Dd, 0);

    ln_kernel<<<NTOK, 256>>>(out, ln2g, ln2b, p_ln2, p_2h, p_2l);
    gate_kernel<<<NTOK * 32 / 256, 256>>>(p_ln2, Wg, bg);
    gemm_mma<<<dim3(8, 64, 8), 256, GSMEM>>>(p_2h, p_2l, p_weh, p_wel, be,
                                             nullptr, nullptr, 0, HIDs, 1);
    fuse_kernel<<<NTOK * HIDs / 1024, 256>>>(out);
    if (out_size > NTOK * Dd) fin_kernel<<<1, 1>>>(out);
}